// round 15
// baseline (speedup 1.0000x reference)
#include <cuda_runtime.h>
#include <cuda_bf16.h>
#include <math.h>
#include <stdint.h>

#define BB 4
#define NTOK 1024
#define CDIM 1024
#define NH 16
#define HD 64
#define KCL 8
#define NBH (BB*NH)
#define NROWS (BB*NH*NTOK)
#define M_ALL (BB*NTOK)

// ---------------- scratch (static device globals) ----------------------------
__device__ __align__(256) float g_th[NROWS];
__device__ float g_zcp[256];
__device__ __align__(256) __nv_bfloat16 g_xh[M_ALL*CDIM];
__device__ __align__(256) __nv_bfloat16 g_xl[M_ALL*CDIM];
__device__ __align__(256) __nv_bfloat16 g_wqh[3072*1024];
__device__ __align__(256) __nv_bfloat16 g_wql[3072*1024];
__device__ __align__(256) __nv_bfloat16 g_wph[1024*1024];
__device__ __align__(256) __nv_bfloat16 g_wpl[1024*1024];
__device__ __align__(256) __nv_bfloat16 g_ohh[M_ALL*CDIM];
__device__ __align__(256) __nv_bfloat16 g_ohl[M_ALL*CDIM];
__device__ __align__(256) __nv_bfloat16 g_qh[NROWS*HD], g_ql[NROWS*HD];
__device__ __align__(256) __nv_bfloat16 g_kh[NROWS*HD], g_kl[NROWS*HD];
__device__ __align__(256) __nv_bfloat16 g_vh[NROWS*HD], g_vl[NROWS*HD];
__device__ __align__(256) __nv_bfloat16 g_vth[NROWS*HD], g_vtl[NROWS*HD];
__device__ __align__(256) __nv_bfloat16 g_zbh[NROWS*16], g_zbl[NROWS*16];
__device__ __align__(256) __nv_bfloat16 g_zjh[NROWS*16], g_zjl[NROWS*16];

// ---------------- helpers ----------------------------------------------------
__device__ __forceinline__ uint32_t smem_u32(const void* p) {
    uint32_t a;
    asm("{ .reg .u64 t; cvta.to.shared.u64 t, %1; cvt.u32.u64 %0, t; }"
        : "=r"(a) : "l"(p));
    return a;
}
__device__ __forceinline__ float fast_tanh(float x) {
    float r;
    asm("tanh.approx.f32 %0, %1;" : "=f"(r) : "f"(x));
    return r;
}
#define CP_ASYNC16(dst, src) \
    asm volatile("cp.async.cg.shared.global [%0], [%1], 16;" :: "r"(dst), "l"(src))
#define CP_COMMIT() asm volatile("cp.async.commit_group;" ::: "memory")
#define CP_WAIT(n)  asm volatile("cp.async.wait_group %0;" :: "n"(n) : "memory")

__device__ __forceinline__ void ldm_x4(uint32_t& r0, uint32_t& r1, uint32_t& r2,
                                       uint32_t& r3, uint32_t addr) {
    asm volatile("ldmatrix.sync.aligned.m8n8.x4.shared.b16 {%0,%1,%2,%3}, [%4];"
                 : "=r"(r0), "=r"(r1), "=r"(r2), "=r"(r3) : "r"(addr));
}
__device__ __forceinline__ void mma_bf16(float* c, const uint32_t* a, const uint32_t* b) {
    asm volatile(
        "mma.sync.aligned.m16n8k16.row.col.f32.bf16.bf16.f32 "
        "{%0,%1,%2,%3}, {%4,%5,%6,%7}, {%8,%9}, {%0,%1,%2,%3};"
        : "+f"(c[0]), "+f"(c[1]), "+f"(c[2]), "+f"(c[3])
        : "r"(a[0]), "r"(a[1]), "r"(a[2]), "r"(a[3]), "r"(b[0]), "r"(b[1]));
}
__device__ __forceinline__ void split_bf16(float v, __nv_bfloat16& hi, __nv_bfloat16& lo) {
    hi = __float2bfloat16(v);
    lo = __float2bfloat16(v - __bfloat162float(hi));
}
__device__ __forceinline__ void pack_hl(float x, float y, uint32_t& hi, uint32_t& lo) {
    __nv_bfloat16 hx, lx, hy, ly;
    split_bf16(x, hx, lx);
    split_bf16(y, hy, ly);
    __nv_bfloat162 h2(hx, hy), l2(lx, ly);
    hi = *(uint32_t*)&h2;
    lo = *(uint32_t*)&l2;
}

// ---------------- prep_all: convert_x (bid<4096) | transW Wqkv (else) --------
__global__ __launch_bounds__(256) void prep_all(const float* __restrict__ x,
                                                const float* __restrict__ Wq) {
    const int bid = blockIdx.x;
    if (bid < 4096) {
        int i = (bid * 256 + threadIdx.x) * 4;
        float4 v = *(const float4*)&x[i];
        float vals[4] = {v.x, v.y, v.z, v.w};
        __nv_bfloat16 h[4], l[4];
        #pragma unroll
        for (int c = 0; c < 4; c++) split_bf16(vals[c], h[c], l[c]);
        *(__nv_bfloat162*)&g_xh[i]     = __nv_bfloat162(h[0], h[1]);
        *(__nv_bfloat162*)&g_xh[i + 2] = __nv_bfloat162(h[2], h[3]);
        *(__nv_bfloat162*)&g_xl[i]     = __nv_bfloat162(l[0], l[1]);
        *(__nv_bfloat162*)&g_xl[i + 2] = __nv_bfloat162(l[2], l[3]);
    } else {
        __shared__ float s[32][33];
        const int b2 = bid - 4096;
        const int n0 = (b2 % 96) * 32, k0 = (b2 / 96) * 32;
        const int tx = threadIdx.x & 31, ty = threadIdx.x >> 5;
        #pragma unroll
        for (int i = 0; i < 4; i++)
            s[ty + i * 8][tx] = Wq[(size_t)(k0 + ty + i * 8) * 3072 + n0 + tx];
        __syncthreads();
        #pragma unroll
        for (int i = 0; i < 4; i++) {
            int n = ty + i * 8;
            float v = s[tx][n];
            __nv_bfloat16 hh, ll;
            split_bf16(v, hh, ll);
            g_wqh[(size_t)(n0 + n) * 1024 + k0 + tx] = hh;
            g_wql[(size_t)(n0 + n) * 1024 + k0 + tx] = ll;
        }
    }
}

// ---------------- transW (Wproj) ---------------------------------------------
__global__ void transW(const float* __restrict__ W) {
    __shared__ float s[32][33];
    const int n0 = blockIdx.x * 32, k0 = blockIdx.y * 32;
    const int tx = threadIdx.x, ty = threadIdx.y;
    #pragma unroll
    for (int i = 0; i < 4; i++)
        s[ty + i * 8][tx] = W[(size_t)(k0 + ty + i * 8) * 1024 + n0 + tx];
    __syncthreads();
    #pragma unroll
    for (int i = 0; i < 4; i++) {
        int n = ty + i * 8;
        float v = s[tx][n];
        __nv_bfloat16 hh, ll;
        split_bf16(v, hh, ll);
        g_wph[(size_t)(n0 + n) * 1024 + k0 + tx] = hh;
        g_wpl[(size_t)(n0 + n) * 1024 + k0 + tx] = ll;
    }
}

// ---------------- tensor-core bf16x3 GEMM, 128x128x32 tiles, 2-stage ---------
#define ROWB 80
#define TILE_B (128 * ROWB)
#define STAGE_B (4 * TILE_B)
#define MMA_SMEM (2 * STAGE_B)

__device__ __forceinline__ void ld_stage(uint32_t sb, int stage,
        const __nv_bfloat16* __restrict__ Ah, const __nv_bfloat16* __restrict__ Al,
        const __nv_bfloat16* __restrict__ Bh, const __nv_bfloat16* __restrict__ Bl,
        int m0, int n0, int kc, int t) {
    const int row = t >> 2, chunk = t & 3;
    const uint32_t base = sb + stage * STAGE_B;
    const uint32_t soff = row * ROWB + chunk * 16;
    const size_t goffA = (size_t)(m0 + row) * 1024 + kc + chunk * 8;
    const size_t goffB = (size_t)(n0 + row) * 1024 + kc + chunk * 8;
    #pragma unroll
    for (int i = 0; i < 2; i++) {
        const uint32_t so = soff + i * 64 * ROWB;
        const size_t ga = goffA + (size_t)i * 64 * 1024;
        const size_t gb = goffB + (size_t)i * 64 * 1024;
        CP_ASYNC16(base + 0 * TILE_B + so, Ah + ga);
        CP_ASYNC16(base + 1 * TILE_B + so, Al + ga);
        CP_ASYNC16(base + 2 * TILE_B + so, Bh + gb);
        CP_ASYNC16(base + 3 * TILE_B + so, Bl + gb);
    }
}

__global__ __launch_bounds__(256) void mma_gemm(const float* __restrict__ bias,
                                                float* __restrict__ outp, int mode) {
    extern __shared__ char sm[];
    const uint32_t sb = smem_u32(sm);
    const int t = threadIdx.x, wid = t >> 5, lane = t & 31;
    const int wm = wid >> 2, wn = wid & 3;
    const int n0 = blockIdx.x * 128, m0 = blockIdx.y * 128;

    const __nv_bfloat16* Ah = mode ? g_ohh : g_xh;
    const __nv_bfloat16* Al = mode ? g_ohl : g_xl;
    const __nv_bfloat16* Bh = mode ? g_wph : g_wqh;
    const __nv_bfloat16* Bl = mode ? g_wpl : g_wql;

    float acc[4][4][4];
    #pragma unroll
    for (int mi = 0; mi < 4; mi++)
        #pragma unroll
        for (int ni = 0; ni < 4; ni++)
            #pragma unroll
            for (int r = 0; r < 4; r++) acc[mi][ni][r] = 0.0f;

    const uint32_t a_row = wm * 64 + (lane & 15);
    const uint32_t a_kb  = (lane >> 4) * 16;
    const uint32_t b_row16 = (lane & 7) + ((lane >> 4) & 1) * 8;
    const uint32_t b_kb  = ((lane >> 3) & 1) * 16;

    ld_stage(sb, 0, Ah, Al, Bh, Bl, m0, n0, 0, t);
    CP_COMMIT();

    for (int kb = 0; kb < 32; kb++) {
        CP_WAIT(0);
        __syncthreads();
        if (kb + 1 < 32) {
            ld_stage(sb, (kb + 1) & 1, Ah, Al, Bh, Bl, m0, n0, (kb + 1) * 32, t);
            CP_COMMIT();
        }

        const uint32_t st = sb + (kb & 1) * STAGE_B;
        #pragma unroll
        for (int ks = 0; ks < 2; ks++) {
            const uint32_t kbyte = ks * 32;
            uint32_t afh[4][4], afl[4][4], bfh[2][4], bfl[2][4];
            #pragma unroll
            for (int mi = 0; mi < 4; mi++) {
                const uint32_t ar = st + (a_row + mi * 16) * ROWB + kbyte + a_kb;
                ldm_x4(afh[mi][0], afh[mi][1], afh[mi][2], afh[mi][3], ar);
                ldm_x4(afl[mi][0], afl[mi][1], afl[mi][2], afl[mi][3], ar + TILE_B);
            }
            #pragma unroll
            for (int np = 0; np < 2; np++) {
                const uint32_t br = st + 2 * TILE_B +
                    (wn * 32 + np * 16 + b_row16) * ROWB + kbyte + b_kb;
                ldm_x4(bfh[np][0], bfh[np][1], bfh[np][2], bfh[np][3], br);
                ldm_x4(bfl[np][0], bfl[np][1], bfl[np][2], bfl[np][3], br + TILE_B);
            }
            #pragma unroll
            for (int mi = 0; mi < 4; mi++)
                #pragma unroll
                for (int np = 0; np < 2; np++)
                    #pragma unroll
                    for (int hh = 0; hh < 2; hh++) {
                        float* a4 = acc[mi][np * 2 + hh];
                        mma_bf16(a4, afh[mi], &bfh[np][hh * 2]);
                        mma_bf16(a4, afh[mi], &bfl[np][hh * 2]);
                        mma_bf16(a4, afl[mi], &bfh[np][hh * 2]);
                    }
        }
    }

    const int er = lane >> 2, ec = (lane & 3) * 2;
    #pragma unroll
    for (int mi = 0; mi < 4; mi++) {
        #pragma unroll
        for (int half = 0; half < 2; half++) {
            const int m = m0 + wm * 64 + mi * 16 + er + half * 8;
            #pragma unroll
            for (int ni = 0; ni < 4; ni++) {
                const float v0 = acc[mi][ni][half * 2];
                const float v1 = acc[mi][ni][half * 2 + 1];
                const int col = n0 + wn * 32 + ni * 8 + ec;
                if (mode == 0) {
                    const int b = m >> 10, n = m & 1023;
                    const int which = col >> 10, rem = col & 1023;
                    const int hh = rem >> 6, d = rem & 63;
                    const size_t idx = (size_t)(((b << 4) + hh) * 1024 + n) * 64 + d;
                    uint32_t hi, lo;
                    pack_hl(v0, v1, hi, lo);
                    if (which == 0) {
                        *(uint32_t*)&g_qh[idx] = hi; *(uint32_t*)&g_ql[idx] = lo;
                    } else if (which == 1) {
                        *(uint32_t*)&g_kh[idx] = hi; *(uint32_t*)&g_kl[idx] = lo;
                    } else {
                        *(uint32_t*)&g_vh[idx] = hi; *(uint32_t*)&g_vl[idx] = lo;
                    }
                } else {
                    float2 w = make_float2(v0 + bias[col], v1 + bias[col + 1]);
                    *(float2*)&outp[(size_t)m * 1024 + col] = w;
                }
            }
        }
    }
}

// ---------------- zv_kernel: zkernel (bid<256) | vtrans (else) ---------------
__global__ __launch_bounds__(256) void zv_kernel(const float* __restrict__ Wg,
                                                 const float* __restrict__ bg,
                                                 const float* __restrict__ Wt,
                                                 const float* __restrict__ bt,
                                                 const float* __restrict__ affB) {
    const int bid = blockIdx.x;
    if (bid < 256) {
        const int r = bid * 256 + threadIdx.x;
        const int h = (r >> 10) & (NH - 1);
        const __nv_bfloat16* qh = g_qh + (size_t)r * HD;
        const __nv_bfloat16* ql = g_ql + (size_t)r * HD;

        float g[KCL];
        #pragma unroll
        for (int l = 0; l < KCL; l++) g[l] = bg[l];
        float th = bt[0];
        for (int k = 0; k < HD; k++) {
            const float qv = __bfloat162float(qh[k]) + __bfloat162float(ql[k]);
            th += qv * Wt[k];
            #pragma unroll
            for (int l = 0; l < KCL; l++) g[l] += qv * Wg[k * KCL + l];
        }
        float mx = g[0];
        #pragma unroll
        for (int l = 1; l < KCL; l++) mx = fmaxf(mx, g[l]);
        float s = 0.0f;
        #pragma unroll
        for (int l = 0; l < KCL; l++) { g[l] = __expf(g[l] - mx); s += g[l]; }
        const float inv = 1.0f / s;
        float ent = 0.0f;
        #pragma unroll
        for (int l = 0; l < KCL; l++) {
            const float z = g[l] * inv;
            g[l] = z;
            ent -= z * logf(z + 1e-8f);
        }
        float zB[KCL];
        #pragma unroll
        for (int l = 0; l < KCL; l++) zB[l] = 0.0f;
        #pragma unroll
        for (int k = 0; k < KCL; k++) {
            const float zk = g[k];
            #pragma unroll
            for (int l = 0; l < KCL; l++) {
                const float a = affB[h * 64 + k * KCL + l];
                zB[l] += zk / (1.0f + __expf(-a));
            }
        }
        g_th[r] = fmaxf(th, 0.0f);
        {
            union { __nv_bfloat16 hb[16]; uint4 v[2]; } zh, zl, bh2, bl2;
            #pragma unroll
            for (int l = 0; l < KCL; l++) {
                split_bf16(g[l], zh.hb[l], zl.hb[l]);
                split_bf16(zB[l], bh2.hb[l], bl2.hb[l]);
            }
            #pragma unroll
            for (int l = KCL; l < 16; l++) {
                zh.hb[l] = __float2bfloat16(0.0f); zl.hb[l] = __float2bfloat16(0.0f);
                bh2.hb[l] = __float2bfloat16(0.0f); bl2.hb[l] = __float2bfloat16(0.0f);
            }
            *(uint4*)&g_zjh[r * 16] = zh.v[0];  *(uint4*)&g_zjh[r * 16 + 8] = zh.v[1];
            *(uint4*)&g_zjl[r * 16] = zl.v[0];  *(uint4*)&g_zjl[r * 16 + 8] = zl.v[1];
            *(uint4*)&g_zbh[r * 16] = bh2.v[0]; *(uint4*)&g_zbh[r * 16 + 8] = bh2.v[1];
            *(uint4*)&g_zbl[r * 16] = bl2.v[0]; *(uint4*)&g_zbl[r * 16 + 8] = bl2.v[1];
        }

        __shared__ float red[256];
        red[threadIdx.x] = ent;
        __syncthreads();
        for (int s2 = 128; s2 > 0; s2 >>= 1) {
            if (threadIdx.x < s2) red[threadIdx.x] += red[threadIdx.x + s2];
            __syncthreads();
        }
        if (threadIdx.x == 0) g_zcp[bid] = red[0];
    } else {
        __shared__ __nv_bfloat16 s[32][72];
        const int b2 = bid - 256;
        const int bh = b2 >> 5, m0 = (b2 & 31) * 32;
        const int t = threadIdx.x;
        #pragma unroll
        for (int which = 0; which < 2; which++) {
            const __nv_bfloat16* src = which ? g_vl : g_vh;
            __nv_bfloat16* dst = which ? g_vtl : g_vth;
            const int row = t >> 3, c = (t & 7) * 8;
            *(uint4*)&s[row][c] =
                *(const uint4*)&src[((size_t)bh * 1024 + m0 + row) * 64 + c];
            __syncthreads();
            const int d = t >> 2, ms = (t & 3) * 8;
            __nv_bfloat16 tmp[8];
            #pragma unroll
            for (int i = 0; i < 8; i++) tmp[i] = s[ms + i][d];
            *(uint4*)&dst[((size_t)bh * 64 + d) * 1024 + m0 + ms] = *(uint4*)tmp;
            __syncthreads();
        }
    }
}

// ---------------- fused attention: 4 warps x 32 q-rows, 32-key chunks --------
// smem (bytes, per CTA ~95KB -> 2 CTAs/SM):
//  Qh 0..18431, Ql 18432..36863          (128 rows x 144B)
//  K stages @36864: stage 9216 (hi 0 / lo 4608), x2   -> 55296
//  V stages @55296: stage 10240 (hi 0 / lo 5120), x2  -> 75776
//  ZJ stages @75776: stage 3072 (hi 0 / lo 1536), x2  -> 81920
//  THJ @81920: 128 x2                                 -> 82176
//  ZBI @82176: hi 6144 + lo 6144                      -> 94464
//  THI @94464: 512                                    -> 94976
#define FA_QROWB 144
#define FA_KROWB 144
#define FA_VROWB 80
#define FA_ZROWB 48
#define FA_SK    36864
#define FA_KST   9216
#define FA_SV    55296
#define FA_VST   10240
#define FA_SZJ   75776
#define FA_ZST   3072
#define FA_STHJ  81920
#define FA_SZBI  82176
#define FA_STHI  94464
#define FA_SMEM  94976

__device__ __forceinline__ void fa_ld_chunk(uint32_t sb, int stage, int bh,
                                            int ch, int t) {
    const uint32_t kbase = sb + FA_SK + stage * FA_KST;
    const size_t kg = ((size_t)bh * 1024 + ch * 32) * 64;
    #pragma unroll
    for (int i = 0; i < 2; i++) {
        const int u = t + i * 128;
        const int row = u >> 3, c = u & 7;
        const uint32_t so = kbase + row * FA_KROWB + c * 16;
        CP_ASYNC16(so,        g_kh + kg + row * 64 + c * 8);
        CP_ASYNC16(so + 4608, g_kl + kg + row * 64 + c * 8);
    }
    const uint32_t vbase = sb + FA_SV + stage * FA_VST;
    const size_t vg = (size_t)bh * 64 * 1024 + ch * 32;
    #pragma unroll
    for (int i = 0; i < 2; i++) {
        const int u = t + i * 128;
        const int row = u >> 2, c = u & 3;
        const uint32_t so = vbase + row * FA_VROWB + c * 16;
        CP_ASYNC16(so,        g_vth + vg + (size_t)row * 1024 + c * 8);
        CP_ASYNC16(so + 5120, g_vtl + vg + (size_t)row * 1024 + c * 8);
    }
    if (t < 64) {
        const int row = t >> 1, half = t & 1;
        const size_t zg = ((size_t)bh * 1024 + ch * 32 + row) * 16 + half * 8;
        const uint32_t so = sb + FA_SZJ + stage * FA_ZST + row * FA_ZROWB + half * 16;
        CP_ASYNC16(so,        g_zjh + zg);
        CP_ASYNC16(so + 1536, g_zjl + zg);
    }
    if (t < 8)
        CP_ASYNC16(sb + FA_STHJ + stage * 128 + t * 16,
                   g_th + (size_t)bh * 1024 + ch * 32 + t * 4);
}

__global__ __launch_bounds__(128, 2) void fused_attn(float* __restrict__ cp_out,
                                                     const float* __restrict__ p_cps,
                                                     const int* __restrict__ p_flag,
                                                     const int* __restrict__ p_dcmm) {
    extern __shared__ char sm[];
    const uint32_t sb = smem_u32(sm);
    const int t = threadIdx.x, wid = t >> 5, lane = t & 31;
    const int bh = blockIdx.x, m0 = blockIdx.y * 128;

    // Q tile (128 rows) + zB tile + thi (once)
    {
        const size_t qb = ((size_t)bh * 1024 + m0) * 64;
        #pragma unroll
        for (int i = 0; i < 8; i++) {
            const int u = t + i * 128;
            const int row = u >> 3, c = u & 7;
            *(uint4*)(sm + row * FA_QROWB + c * 16) =
                *(const uint4*)(g_qh + qb + row * 64 + c * 8);
            *(uint4*)(sm + 18432 + row * FA_QROWB + c * 16) =
                *(const uint4*)(g_ql + qb + row * 64 + c * 8);
        }
        #pragma unroll
        for (int i = 0; i < 2; i++) {
            const int u = t + i * 128;
            const int row = u >> 1, half = u & 1;
            const size_t zg = ((size_t)bh * 1024 + m0 + row) * 16 + half * 8;
            *(uint4*)(sm + FA_SZBI + row * FA_ZROWB + half * 16) =
                *(const uint4*)(g_zbh + zg);
            *(uint4*)(sm + FA_SZBI + 6144 + row * FA_ZROWB + half * 16) =
                *(const uint4*)(g_zbl + zg);
        }
    }
    ((float*)(sm + FA_STHI))[t] = g_th[(size_t)bh * 1024 + m0 + t];
    fa_ld_chunk(sb, 0, bh, 0, t);
    CP_COMMIT();
    __syncthreads();

    // persistent zB fragments per m-tile
    uint32_t azh[2][4], azl[2][4];
    const uint32_t a_kb = (lane >> 4) * 16;
    #pragma unroll
    for (int mi = 0; mi < 2; mi++) {
        const uint32_t ar = wid * 32 + mi * 16 + (lane & 15);
        const uint32_t zr = sb + FA_SZBI + ar * FA_ZROWB + a_kb;
        ldm_x4(azh[mi][0], azh[mi][1], azh[mi][2], azh[mi][3], zr);
        ldm_x4(azl[mi][0], azl[mi][1], azl[mi][2], azl[mi][3], zr + 6144);
    }
    const int er = lane >> 2;
    const float gate = (p_flag[0] != 0 && p_dcmm[0] != 0) ? 1.0f : 0.0f;
    const float cps = p_cps[0] * gate;
    float fi[2][2];
    #pragma unroll
    for (int mi = 0; mi < 2; mi++) {
        fi[mi][0] = cps * ((float*)(sm + FA_STHI))[wid * 32 + mi * 16 + er];
        fi[mi][1] = cps * ((float*)(sm + FA_STHI))[wid * 32 + mi * 16 + er + 8];
    }

    float o[2][8][4];
    #pragma unroll
    for (int mi = 0; mi < 2; mi++)
        #pragma unroll
        for (int ni = 0; ni < 8; ni++)
            #pragma unroll
            for (int r = 0; r < 4; r++) o[mi][ni][r] = 0.0f;
    float mr[2][2], lr[2][2];
    #pragma unroll
    for (int mi = 0; mi < 2; mi++) {
        mr[mi][0] = -1e30f; mr[mi][1] = -1e30f;
        lr[mi][0] = 0.0f;   lr[mi][1] = 0.0f;
    }

    const uint32_t b_row16 = (lane & 7) + ((lane >> 4) & 1) * 8;
    const uint32_t b_kb = ((lane >> 3) & 1) * 16;
    const int c0l = (lane & 3) * 2;
    const long long cpbase = (long long)bh << 20;

    for (int ch = 0; ch < 32; ch++) {
        CP_WAIT(0);
        __syncthreads();
        if (ch < 31) {
            fa_ld_chunk(sb, (ch + 1) & 1, bh, ch + 1, t);
            CP_COMMIT();
        }

        const uint32_t kst = sb + FA_SK + (ch & 1) * FA_KST;
        const uint32_t vst = sb + FA_SV + (ch & 1) * FA_VST;
        const uint32_t zjst = sb + FA_SZJ + (ch & 1) * FA_ZST;
        const float* thj = (const float*)(sm + FA_STHJ + (ch & 1) * 128);

        // ---- S = Q K^T (3-pass hi/lo), B-frags shared across m-tiles ----
        float s[2][4][4];
        #pragma unroll
        for (int mi = 0; mi < 2; mi++)
            #pragma unroll
            for (int ni = 0; ni < 4; ni++)
                #pragma unroll
                for (int r = 0; r < 4; r++) s[mi][ni][r] = 0.0f;

        #pragma unroll
        for (int ks = 0; ks < 4; ks++) {
            uint32_t bkh[2][4], bkl[2][4];
            #pragma unroll
            for (int np = 0; np < 2; np++) {
                const uint32_t br = kst + (np * 16 + b_row16) * FA_KROWB + ks * 32 + b_kb;
                ldm_x4(bkh[np][0], bkh[np][1], bkh[np][2], bkh[np][3], br);
                ldm_x4(bkl[np][0], bkl[np][1], bkl[np][2], bkl[np][3], br + 4608);
            }
            #pragma unroll
            for (int mi = 0; mi < 2; mi++) {
                uint32_t aqh[4], aql[4];
                const uint32_t ar = sb + (wid * 32 + mi * 16 + (lane & 15)) * FA_QROWB
                                    + ks * 32 + a_kb;
                ldm_x4(aqh[0], aqh[1], aqh[2], aqh[3], ar);
                ldm_x4(aql[0], aql[1], aql[2], aql[3], ar + 18432);
                #pragma unroll
                for (int np = 0; np < 2; np++)
                    #pragma unroll
                    for (int hh = 0; hh < 2; hh++) {
                        float* s4 = s[mi][np * 2 + hh];
                        mma_bf16(s4, aqh, &bkh[np][hh * 2]);
                        mma_bf16(s4, aqh, &bkl[np][hh * 2]);
                        mma_bf16(s4, aql, &bkh[np][hh * 2]);
                    }
            }
        }

        // ---- bias via MMA (zB @ z^T), tanh, cp write, chunk max ----
        float cmax[2][2];
        #pragma unroll
        for (int mi = 0; mi < 2; mi++) { cmax[mi][0] = -1e30f; cmax[mi][1] = -1e30f; }
        #pragma unroll
        for (int np = 0; np < 2; np++) {
            uint32_t zh4[4], zl4[4];
            const uint32_t zr = zjst + (np * 16 + b_row16) * FA_ZROWB + b_kb;
            ldm_x4(zh4[0], zh4[1], zh4[2], zh4[3], zr);
            ldm_x4(zl4[0], zl4[1], zl4[2], zl4[3], zr + 1536);
            #pragma unroll
            for (int mi = 0; mi < 2; mi++)
                #pragma unroll
                for (int hh = 0; hh < 2; hh++) {
                    const int ni = np * 2 + hh;
                    const int c0 = ni * 8 + c0l;
                    float d[4] = {0.0f, 0.0f, 0.0f, 0.0f};
                    mma_bf16(d, azh[mi], &zh4[hh * 2]);
                    mma_bf16(d, azh[mi], &zl4[hh * 2]);
                    mma_bf16(d, azl[mi], &zh4[hh * 2]);
                    const float th0 = thj[c0], th1 = thj[c0 + 1];
                    const float b00 = fi[mi][0] * th0 * fast_tanh(d[0]);
                    const float b01 = fi[mi][0] * th1 * fast_tanh(d[1]);
                    const float b10 = fi[mi][1] * th0 * fast_tanh(d[2]);
                    const float b11 = fi[mi][1] * th1 * fast_tanh(d[3]);
                    const int row = m0 + wid * 32 + mi * 16 + er;
                    const long long off = cpbase + (long long)row * 1024 + ch * 32 + c0;
                    cp_out[off] = b00; cp_out[off + 1] = b01;
                    cp_out[off + 8192] = b10; cp_out[off + 8193] = b11;
                    float* s4 = s[mi][ni];
                    s4[0] = s4[0] * 0.125f + b00;
                    s4[1] = s4[1] * 0.125f + b01;
                    s4[2] = s4[2] * 0.125f + b10;
                    s4[3] = s4[3] * 0.125f + b11;
                    cmax[mi][0] = fmaxf(cmax[mi][0], fmaxf(s4[0], s4[1]));
                    cmax[mi][1] = fmaxf(cmax[mi][1], fmaxf(s4[2], s4[3]));
                }
        }
        #pragma unroll
        for (int mi = 0; mi < 2; mi++)
            #pragma unroll
            for (int hf = 0; hf < 2; hf++) {
                float cm = cmax[mi][hf];
                cm = fmaxf(cm, __shfl_xor_sync(0xffffffffu, cm, 1));
                cm = fmaxf(cm, __shfl_xor_sync(0xffffffffu, cm, 2));
                cmax[mi][hf] = cm;
            }

        float sc[2][2];
        #pragma unroll
        for (int mi = 0; mi < 2; mi++)
            #pragma unroll
            for (int hf = 0; hf < 2; hf++) {
                const float M = fmaxf(mr[mi][hf], cmax[mi][hf]);
                sc[mi][hf] = __expf(mr[mi][hf] - M);
                mr[mi][hf] = M;
            }

        float ls[2][2] = {{0.0f, 0.0f}, {0.0f, 0.0f}};
        #pragma unroll
        for (int mi = 0; mi < 2; mi++)
            #pragma unroll
            for (int ni = 0; ni < 4; ni++) {
                float* s4 = s[mi][ni];
                s4[0] = __expf(s4[0] - mr[mi][0]);
                s4[1] = __expf(s4[1] - mr[mi][0]);
                s4[2] = __expf(s4[2] - mr[mi][1]);
                s4[3] = __expf(s4[3] - mr[mi][1]);
                ls[mi][0] += s4[0] + s4[1];
                ls[mi][1] += s4[2] + s4[3];
            }
        #pragma unroll
        for (int mi = 0; mi < 2; mi++)
            #pragma unroll
            for (int hf = 0; hf < 2; hf++) {
                float l = ls[mi][hf];
                l += __shfl_xor_sync(0xffffffffu, l, 1);
                l += __shfl_xor_sync(0xffffffffu, l, 2);
                lr[mi][hf] = lr[mi][hf] * sc[mi][hf] + l;
            }
        #pragma unroll
        for (int mi = 0; mi < 2; mi++)
            #pragma unroll
            for (int ni = 0; ni < 8; ni++) {
                o[mi][ni][0] *= sc[mi][0]; o[mi][ni][1] *= sc[mi][0];
                o[mi][ni][2] *= sc[mi][1]; o[mi][ni][3] *= sc[mi][1];
            }

        // ---- O += P V, V b-frags shared across m-tiles ----
        uint32_t ah[2][2][4], al[2][2][4];
        #pragma unroll
        for (int mi = 0; mi < 2; mi++)
            #pragma unroll
            for (int ks = 0; ks < 2; ks++) {
                pack_hl(s[mi][2 * ks][0],     s[mi][2 * ks][1],     ah[mi][ks][0], al[mi][ks][0]);
                pack_hl(s[mi][2 * ks][2],     s[mi][2 * ks][3],     ah[mi][ks][1], al[mi][ks][1]);
                pack_hl(s[mi][2 * ks + 1][0], s[mi][2 * ks + 1][1], ah[mi][ks][2], al[mi][ks][2]);
                pack_hl(s[mi][2 * ks + 1][2], s[mi][2 * ks + 1][3], ah[mi][ks][3], al[mi][ks][3]);
            }
        #pragma unroll
        for (int ks = 0; ks < 2; ks++)
            #pragma unroll
            for (int np = 0; np < 4; np++) {
                uint32_t bvh[4], bvl[4];
                const uint32_t br = vst + (np * 16 + b_row16) * FA_VROWB + ks * 32 + b_kb;
                ldm_x4(bvh[0], bvh[1], bvh[2], bvh[3], br);
                ldm_x4(bvl[0], bvl[1], bvl[2], bvl[3], br + 5120);
                #pragma unroll
                for (int mi = 0; mi < 2; mi++)
                    #pragma unroll
                    for (int hh = 0; hh < 2; hh++) {
                        float* o4 = o[mi][np * 2 + hh];
                        mma_bf16(o4, ah[mi][ks], &bvh[hh * 2]);
                        mma_bf16(o4, ah[mi][ks], &bvl[hh * 2]);
                        mma_bf16(o4, al[mi][ks], &bvh[hh * 2]);
                    }
            }
    }

    // ---- finalize O, write hi/lo bf16 ----
    const int b = bh >> 4, h = bh & 15;
    #pragma unroll
    for (int mi = 0; mi < 2; mi++) {
        const float inv0 = 1.0f / lr[mi][0], inv1 = 1.0f / lr[mi][1];
        const int row = m0 + wid * 32 + mi * 16 + er;
        #pragma unroll
        for (int ni = 0; ni < 8; ni++) {
            const int d = ni * 8 + c0l;
            const size_t ro = ((size_t)(b * 1024 + row)) * 1024 + h * 64 + d;
            uint32_t hi, lo;
            pack_hl(o[mi][ni][0] * inv0, o[mi][ni][1] * inv0, hi, lo);
            *(uint32_t*)&g_ohh[ro] = hi;
            *(uint32_t*)&g_ohl[ro] = lo;
            pack_hl(o[mi][ni][2] * inv1, o[mi][ni][3] * inv1, hi, lo);
            *(uint32_t*)&g_ohh[ro + 8 * 1024] = hi;
            *(uint32_t*)&g_ohl[ro + 8 * 1024] = lo;
        }
    }
}

// ---------------- scalar outputs ---------------------------------------------
__global__ void finalize(float* __restrict__ out,
                         const int* __restrict__ p_flag,
                         const int* __restrict__ p_dcmm) {
    __shared__ float red[256];
    red[threadIdx.x] = g_zcp[threadIdx.x];
    __syncthreads();
    for (int s2 = 128; s2 > 0; s2 >>= 1) {
        if (threadIdx.x < s2) red[threadIdx.x] += red[threadIdx.x + s2];
        __syncthreads();
    }
    if (threadIdx.x == 0) {
        const float gate = (p_flag[0] != 0 && p_dcmm[0] != 0) ? 1.0f : 0.0f;
        out[4194304] = gate * red[0] * (1.0f / 65536.0f);
        out[4194305] = 0.0f;
        out[4194306] = 0.0f;
    }
}

// ---------------------------------------------------------------------------
extern "C" void kernel_launch(void* const* d_in, const int* in_sizes, int n_in,
                              void* d_out, int out_size) {
    const float* x     = (const float*)d_in[0];
    const float* Wqkv  = (const float*)d_in[1];
    const float* Wproj = (const float*)d_in[2];
    const float* bproj = (const float*)d_in[3];
    const float* Wg    = (const float*)d_in[4];
    const float* bg    = (const float*)d_in[5];
    const float* Wt    = (const float*)d_in[6];
    const float* bt    = (const float*)d_in[7];
    const float* affB  = (const float*)d_in[8];
    const float* cps   = (const float*)d_in[9];
    const int*   flag  = (const int*)d_in[10];
    const int*   dcmm  = (const int*)d_in[12];

    float* out = (float*)d_out;
    float* cp  = out + 4194307;

    cudaFuncSetAttribute(mma_gemm, cudaFuncAttributeMaxDynamicSharedMemorySize, MMA_SMEM);
    cudaFuncSetAttribute(fused_attn, cudaFuncAttributeMaxDynamicSharedMemorySize, FA_SMEM);

    prep_all<<<4096 + 3072, 256>>>(x, Wqkv);
    mma_gemm<<<dim3(24, 32), 256, MMA_SMEM>>>(nullptr, nullptr, 0);
    zv_kernel<<<256 + 2048, 256>>>(Wg, bg, Wt, bt, affB);
    fused_attn<<<dim3(64, 8), 128, FA_SMEM>>>(cp, cps, flag, dcmm);
    transW<<<dim3(32, 32), dim3(32, 8)>>>(Wproj);
    mma_gemm<<<dim3(8, 32), 256, MMA_SMEM>>>(bproj, out, 1);
    finalize<<<1, 256>>>(out, flag, dcmm);
}

// round 17
// speedup vs baseline: 1.0476x; 1.0476x over previous
#include <cuda_runtime.h>
#include <cuda_bf16.h>
#include <math.h>
#include <stdint.h>

#define BB 4
#define NTOK 1024
#define CDIM 1024
#define NH 16
#define HD 64
#define KCL 8
#define NBH (BB*NH)
#define NROWS (BB*NH*NTOK)
#define M_ALL (BB*NTOK)

// ---------------- scratch (static device globals) ----------------------------
__device__ __align__(256) float g_th[NROWS];
__device__ float g_zcp[256];
__device__ __align__(256) __nv_bfloat16 g_xh[M_ALL*CDIM];
__device__ __align__(256) __nv_bfloat16 g_xl[M_ALL*CDIM];
__device__ __align__(256) __nv_bfloat16 g_wqh[3072*1024];
__device__ __align__(256) __nv_bfloat16 g_wql[3072*1024];
__device__ __align__(256) __nv_bfloat16 g_wph[1024*1024];
__device__ __align__(256) __nv_bfloat16 g_wpl[1024*1024];
__device__ __align__(256) __nv_bfloat16 g_ohh[M_ALL*CDIM];
__device__ __align__(256) __nv_bfloat16 g_ohl[M_ALL*CDIM];
__device__ __align__(256) __nv_bfloat16 g_qh[NROWS*HD], g_ql[NROWS*HD];
__device__ __align__(256) __nv_bfloat16 g_kh[NROWS*HD], g_kl[NROWS*HD];
__device__ __align__(256) __nv_bfloat16 g_vh[NROWS*HD], g_vl[NROWS*HD];
__device__ __align__(256) __nv_bfloat16 g_vth[NROWS*HD], g_vtl[NROWS*HD];
__device__ __align__(256) __nv_bfloat16 g_zbh[NROWS*16], g_zbl[NROWS*16];
__device__ __align__(256) __nv_bfloat16 g_zjh[NROWS*16], g_zjl[NROWS*16];

// ---------------- helpers ----------------------------------------------------
__device__ __forceinline__ uint32_t smem_u32(const void* p) {
    uint32_t a;
    asm("{ .reg .u64 t; cvta.to.shared.u64 t, %1; cvt.u32.u64 %0, t; }"
        : "=r"(a) : "l"(p));
    return a;
}
__device__ __forceinline__ float fast_tanh(float x) {
    float r;
    asm("tanh.approx.f32 %0, %1;" : "=f"(r) : "f"(x));
    return r;
}
#define CP_ASYNC16(dst, src) \
    asm volatile("cp.async.cg.shared.global [%0], [%1], 16;" :: "r"(dst), "l"(src))
#define CP_COMMIT() asm volatile("cp.async.commit_group;" ::: "memory")
#define CP_WAIT(n)  asm volatile("cp.async.wait_group %0;" :: "n"(n) : "memory")

__device__ __forceinline__ void ldm_x4(uint32_t& r0, uint32_t& r1, uint32_t& r2,
                                       uint32_t& r3, uint32_t addr) {
    asm volatile("ldmatrix.sync.aligned.m8n8.x4.shared.b16 {%0,%1,%2,%3}, [%4];"
                 : "=r"(r0), "=r"(r1), "=r"(r2), "=r"(r3) : "r"(addr));
}
__device__ __forceinline__ void mma_bf16(float* c, const uint32_t* a, const uint32_t* b) {
    asm volatile(
        "mma.sync.aligned.m16n8k16.row.col.f32.bf16.bf16.f32 "
        "{%0,%1,%2,%3}, {%4,%5,%6,%7}, {%8,%9}, {%0,%1,%2,%3};"
        : "+f"(c[0]), "+f"(c[1]), "+f"(c[2]), "+f"(c[3])
        : "r"(a[0]), "r"(a[1]), "r"(a[2]), "r"(a[3]), "r"(b[0]), "r"(b[1]));
}
__device__ __forceinline__ void split_bf16(float v, __nv_bfloat16& hi, __nv_bfloat16& lo) {
    hi = __float2bfloat16(v);
    lo = __float2bfloat16(v - __bfloat162float(hi));
}
__device__ __forceinline__ void pack_hl(float x, float y, uint32_t& hi, uint32_t& lo) {
    __nv_bfloat16 hx, lx, hy, ly;
    split_bf16(x, hx, lx);
    split_bf16(y, hy, ly);
    __nv_bfloat162 h2(hx, hy), l2(lx, ly);
    hi = *(uint32_t*)&h2;
    lo = *(uint32_t*)&l2;
}

// ---------------- prep_all: convert_x (bid<4096) | transW Wqkv (else) --------
__global__ __launch_bounds__(256) void prep_all(const float* __restrict__ x,
                                                const float* __restrict__ Wq) {
    const int bid = blockIdx.x;
    if (bid < 4096) {
        int i = (bid * 256 + threadIdx.x) * 4;
        float4 v = *(const float4*)&x[i];
        float vals[4] = {v.x, v.y, v.z, v.w};
        __nv_bfloat16 h[4], l[4];
        #pragma unroll
        for (int c = 0; c < 4; c++) split_bf16(vals[c], h[c], l[c]);
        *(__nv_bfloat162*)&g_xh[i]     = __nv_bfloat162(h[0], h[1]);
        *(__nv_bfloat162*)&g_xh[i + 2] = __nv_bfloat162(h[2], h[3]);
        *(__nv_bfloat162*)&g_xl[i]     = __nv_bfloat162(l[0], l[1]);
        *(__nv_bfloat162*)&g_xl[i + 2] = __nv_bfloat162(l[2], l[3]);
    } else {
        __shared__ float s[32][33];
        const int b2 = bid - 4096;
        const int n0 = (b2 % 96) * 32, k0 = (b2 / 96) * 32;
        const int tx = threadIdx.x & 31, ty = threadIdx.x >> 5;
        #pragma unroll
        for (int i = 0; i < 4; i++)
            s[ty + i * 8][tx] = Wq[(size_t)(k0 + ty + i * 8) * 3072 + n0 + tx];
        __syncthreads();
        #pragma unroll
        for (int i = 0; i < 4; i++) {
            int n = ty + i * 8;
            float v = s[tx][n];
            __nv_bfloat16 hh, ll;
            split_bf16(v, hh, ll);
            g_wqh[(size_t)(n0 + n) * 1024 + k0 + tx] = hh;
            g_wql[(size_t)(n0 + n) * 1024 + k0 + tx] = ll;
        }
    }
}

// ---------------- transW (Wproj) ---------------------------------------------
__global__ void transW(const float* __restrict__ W) {
    __shared__ float s[32][33];
    const int n0 = blockIdx.x * 32, k0 = blockIdx.y * 32;
    const int tx = threadIdx.x, ty = threadIdx.y;
    #pragma unroll
    for (int i = 0; i < 4; i++)
        s[ty + i * 8][tx] = W[(size_t)(k0 + ty + i * 8) * 1024 + n0 + tx];
    __syncthreads();
    #pragma unroll
    for (int i = 0; i < 4; i++) {
        int n = ty + i * 8;
        float v = s[tx][n];
        __nv_bfloat16 hh, ll;
        split_bf16(v, hh, ll);
        g_wph[(size_t)(n0 + n) * 1024 + k0 + tx] = hh;
        g_wpl[(size_t)(n0 + n) * 1024 + k0 + tx] = ll;
    }
}

// ---------------- tensor-core bf16x3 GEMM, 128x128x32 tiles, 2-stage ---------
#define ROWB 80
#define TILE_B (128 * ROWB)
#define STAGE_B (4 * TILE_B)
#define MMA_SMEM (2 * STAGE_B)

__device__ __forceinline__ void ld_stage(uint32_t sb, int stage,
        const __nv_bfloat16* __restrict__ Ah, const __nv_bfloat16* __restrict__ Al,
        const __nv_bfloat16* __restrict__ Bh, const __nv_bfloat16* __restrict__ Bl,
        int m0, int n0, int kc, int t) {
    const int row = t >> 2, chunk = t & 3;
    const uint32_t base = sb + stage * STAGE_B;
    const uint32_t soff = row * ROWB + chunk * 16;
    const size_t goffA = (size_t)(m0 + row) * 1024 + kc + chunk * 8;
    const size_t goffB = (size_t)(n0 + row) * 1024 + kc + chunk * 8;
    #pragma unroll
    for (int i = 0; i < 2; i++) {
        const uint32_t so = soff + i * 64 * ROWB;
        const size_t ga = goffA + (size_t)i * 64 * 1024;
        const size_t gb = goffB + (size_t)i * 64 * 1024;
        CP_ASYNC16(base + 0 * TILE_B + so, Ah + ga);
        CP_ASYNC16(base + 1 * TILE_B + so, Al + ga);
        CP_ASYNC16(base + 2 * TILE_B + so, Bh + gb);
        CP_ASYNC16(base + 3 * TILE_B + so, Bl + gb);
    }
}

__global__ __launch_bounds__(256) void mma_gemm(const float* __restrict__ bias,
                                                float* __restrict__ outp, int mode) {
    extern __shared__ char sm[];
    const uint32_t sb = smem_u32(sm);
    const int t = threadIdx.x, wid = t >> 5, lane = t & 31;
    const int wm = wid >> 2, wn = wid & 3;
    const int n0 = blockIdx.x * 128, m0 = blockIdx.y * 128;

    const __nv_bfloat16* Ah = mode ? g_ohh : g_xh;
    const __nv_bfloat16* Al = mode ? g_ohl : g_xl;
    const __nv_bfloat16* Bh = mode ? g_wph : g_wqh;
    const __nv_bfloat16* Bl = mode ? g_wpl : g_wql;

    float acc[4][4][4];
    #pragma unroll
    for (int mi = 0; mi < 4; mi++)
        #pragma unroll
        for (int ni = 0; ni < 4; ni++)
            #pragma unroll
            for (int r = 0; r < 4; r++) acc[mi][ni][r] = 0.0f;

    const uint32_t a_row = wm * 64 + (lane & 15);
    const uint32_t a_kb  = (lane >> 4) * 16;
    const uint32_t b_row16 = (lane & 7) + ((lane >> 4) & 1) * 8;
    const uint32_t b_kb  = ((lane >> 3) & 1) * 16;

    ld_stage(sb, 0, Ah, Al, Bh, Bl, m0, n0, 0, t);
    CP_COMMIT();

    for (int kb = 0; kb < 32; kb++) {
        CP_WAIT(0);
        __syncthreads();
        if (kb + 1 < 32) {
            ld_stage(sb, (kb + 1) & 1, Ah, Al, Bh, Bl, m0, n0, (kb + 1) * 32, t);
            CP_COMMIT();
        }

        const uint32_t st = sb + (kb & 1) * STAGE_B;
        #pragma unroll
        for (int ks = 0; ks < 2; ks++) {
            const uint32_t kbyte = ks * 32;
            uint32_t afh[4][4], afl[4][4], bfh[2][4], bfl[2][4];
            #pragma unroll
            for (int mi = 0; mi < 4; mi++) {
                const uint32_t ar = st + (a_row + mi * 16) * ROWB + kbyte + a_kb;
                ldm_x4(afh[mi][0], afh[mi][1], afh[mi][2], afh[mi][3], ar);
                ldm_x4(afl[mi][0], afl[mi][1], afl[mi][2], afl[mi][3], ar + TILE_B);
            }
            #pragma unroll
            for (int np = 0; np < 2; np++) {
                const uint32_t br = st + 2 * TILE_B +
                    (wn * 32 + np * 16 + b_row16) * ROWB + kbyte + b_kb;
                ldm_x4(bfh[np][0], bfh[np][1], bfh[np][2], bfh[np][3], br);
                ldm_x4(bfl[np][0], bfl[np][1], bfl[np][2], bfl[np][3], br + TILE_B);
            }
            #pragma unroll
            for (int mi = 0; mi < 4; mi++)
                #pragma unroll
                for (int np = 0; np < 2; np++)
                    #pragma unroll
                    for (int hh = 0; hh < 2; hh++) {
                        float* a4 = acc[mi][np * 2 + hh];
                        mma_bf16(a4, afh[mi], &bfh[np][hh * 2]);
                        mma_bf16(a4, afh[mi], &bfl[np][hh * 2]);
                        mma_bf16(a4, afl[mi], &bfh[np][hh * 2]);
                    }
        }
    }

    const int er = lane >> 2, ec = (lane & 3) * 2;
    #pragma unroll
    for (int mi = 0; mi < 4; mi++) {
        #pragma unroll
        for (int half = 0; half < 2; half++) {
            const int m = m0 + wm * 64 + mi * 16 + er + half * 8;
            #pragma unroll
            for (int ni = 0; ni < 4; ni++) {
                const float v0 = acc[mi][ni][half * 2];
                const float v1 = acc[mi][ni][half * 2 + 1];
                const int col = n0 + wn * 32 + ni * 8 + ec;
                if (mode == 0) {
                    const int b = m >> 10, n = m & 1023;
                    const int which = col >> 10, rem = col & 1023;
                    const int hh = rem >> 6, d = rem & 63;
                    const size_t idx = (size_t)(((b << 4) + hh) * 1024 + n) * 64 + d;
                    uint32_t hi, lo;
                    pack_hl(v0, v1, hi, lo);
                    if (which == 0) {
                        *(uint32_t*)&g_qh[idx] = hi; *(uint32_t*)&g_ql[idx] = lo;
                    } else if (which == 1) {
                        *(uint32_t*)&g_kh[idx] = hi; *(uint32_t*)&g_kl[idx] = lo;
                    } else {
                        *(uint32_t*)&g_vh[idx] = hi; *(uint32_t*)&g_vl[idx] = lo;
                    }
                } else {
                    float2 w = make_float2(v0 + bias[col], v1 + bias[col + 1]);
                    *(float2*)&outp[(size_t)m * 1024 + col] = w;
                }
            }
        }
    }
}

// ---------------- zv_kernel: zkernel (bid<256) | vtrans (else) ---------------
__global__ __launch_bounds__(256) void zv_kernel(const float* __restrict__ Wg,
                                                 const float* __restrict__ bg,
                                                 const float* __restrict__ Wt,
                                                 const float* __restrict__ bt,
                                                 const float* __restrict__ affB) {
    const int bid = blockIdx.x;
    if (bid < 256) {
        const int r = bid * 256 + threadIdx.x;
        const int h = (r >> 10) & (NH - 1);
        const __nv_bfloat16* qh = g_qh + (size_t)r * HD;
        const __nv_bfloat16* ql = g_ql + (size_t)r * HD;

        float g[KCL];
        #pragma unroll
        for (int l = 0; l < KCL; l++) g[l] = bg[l];
        float th = bt[0];
        for (int k = 0; k < HD; k++) {
            const float qv = __bfloat162float(qh[k]) + __bfloat162float(ql[k]);
            th += qv * Wt[k];
            #pragma unroll
            for (int l = 0; l < KCL; l++) g[l] += qv * Wg[k * KCL + l];
        }
        float mx = g[0];
        #pragma unroll
        for (int l = 1; l < KCL; l++) mx = fmaxf(mx, g[l]);
        float s = 0.0f;
        #pragma unroll
        for (int l = 0; l < KCL; l++) { g[l] = __expf(g[l] - mx); s += g[l]; }
        const float inv = 1.0f / s;
        float ent = 0.0f;
        #pragma unroll
        for (int l = 0; l < KCL; l++) {
            const float z = g[l] * inv;
            g[l] = z;
            ent -= z * logf(z + 1e-8f);
        }
        float zB[KCL];
        #pragma unroll
        for (int l = 0; l < KCL; l++) zB[l] = 0.0f;
        #pragma unroll
        for (int k = 0; k < KCL; k++) {
            const float zk = g[k];
            #pragma unroll
            for (int l = 0; l < KCL; l++) {
                const float a = affB[h * 64 + k * KCL + l];
                zB[l] += zk / (1.0f + __expf(-a));
            }
        }
        g_th[r] = fmaxf(th, 0.0f);
        {
            union { __nv_bfloat16 hb[16]; uint4 v[2]; } zh, zl, bh2, bl2;
            #pragma unroll
            for (int l = 0; l < KCL; l++) {
                split_bf16(g[l], zh.hb[l], zl.hb[l]);
                split_bf16(zB[l], bh2.hb[l], bl2.hb[l]);
            }
            #pragma unroll
            for (int l = KCL; l < 16; l++) {
                zh.hb[l] = __float2bfloat16(0.0f); zl.hb[l] = __float2bfloat16(0.0f);
                bh2.hb[l] = __float2bfloat16(0.0f); bl2.hb[l] = __float2bfloat16(0.0f);
            }
            *(uint4*)&g_zjh[r * 16] = zh.v[0];  *(uint4*)&g_zjh[r * 16 + 8] = zh.v[1];
            *(uint4*)&g_zjl[r * 16] = zl.v[0];  *(uint4*)&g_zjl[r * 16 + 8] = zl.v[1];
            *(uint4*)&g_zbh[r * 16] = bh2.v[0]; *(uint4*)&g_zbh[r * 16 + 8] = bh2.v[1];
            *(uint4*)&g_zbl[r * 16] = bl2.v[0]; *(uint4*)&g_zbl[r * 16 + 8] = bl2.v[1];
        }

        __shared__ float red[256];
        red[threadIdx.x] = ent;
        __syncthreads();
        for (int s2 = 128; s2 > 0; s2 >>= 1) {
            if (threadIdx.x < s2) red[threadIdx.x] += red[threadIdx.x + s2];
            __syncthreads();
        }
        if (threadIdx.x == 0) g_zcp[bid] = red[0];
    } else {
        __shared__ __nv_bfloat16 s[32][72];
        const int b2 = bid - 256;
        const int bh = b2 >> 5, m0 = (b2 & 31) * 32;
        const int t = threadIdx.x;
        #pragma unroll
        for (int which = 0; which < 2; which++) {
            const __nv_bfloat16* src = which ? g_vl : g_vh;
            __nv_bfloat16* dst = which ? g_vtl : g_vth;
            const int row = t >> 3, c = (t & 7) * 8;
            *(uint4*)&s[row][c] =
                *(const uint4*)&src[((size_t)bh * 1024 + m0 + row) * 64 + c];
            __syncthreads();
            const int d = t >> 2, ms = (t & 3) * 8;
            __nv_bfloat16 tmp[8];
            #pragma unroll
            for (int i = 0; i < 8; i++) tmp[i] = s[ms + i][d];
            *(uint4*)&dst[((size_t)bh * 64 + d) * 1024 + m0 + ms] = *(uint4*)tmp;
            __syncthreads();
        }
    }
}

// ---------------- fused attention: 128 thr, 64 q-rows, 32-key chunks ---------
#define FA_QROWB 144
#define FA_KROWB 144
#define FA_VROWB 80
#define FA_ZROWB 48
#define FA_SK    18432
#define FA_KST   9216
#define FA_SV    36864
#define FA_VST   10240
#define FA_SZJ   57344
#define FA_ZST   3072
#define FA_STHJ  63488
#define FA_SZBI  63744
#define FA_STHI  69888
#define FA_SMEM  70144

__device__ __forceinline__ void fa_ld_chunk(uint32_t sb, int stage, int bh,
                                            int ch, int t) {
    const uint32_t kbase = sb + FA_SK + stage * FA_KST;
    const size_t kg = ((size_t)bh * 1024 + ch * 32) * 64;
    #pragma unroll
    for (int i = 0; i < 2; i++) {
        const int u = t + i * 128;
        const int row = u >> 3, c = u & 7;
        const uint32_t so = kbase + row * FA_KROWB + c * 16;
        CP_ASYNC16(so,        g_kh + kg + row * 64 + c * 8);
        CP_ASYNC16(so + 4608, g_kl + kg + row * 64 + c * 8);
    }
    const uint32_t vbase = sb + FA_SV + stage * FA_VST;
    const size_t vg = (size_t)bh * 64 * 1024 + ch * 32;
    #pragma unroll
    for (int i = 0; i < 2; i++) {
        const int u = t + i * 128;
        const int row = u >> 2, c = u & 3;
        const uint32_t so = vbase + row * FA_VROWB + c * 16;
        CP_ASYNC16(so,        g_vth + vg + (size_t)row * 1024 + c * 8);
        CP_ASYNC16(so + 5120, g_vtl + vg + (size_t)row * 1024 + c * 8);
    }
    if (t < 64) {
        const int row = t >> 1, half = t & 1;
        const size_t zg = ((size_t)bh * 1024 + ch * 32 + row) * 16 + half * 8;
        const uint32_t so = sb + FA_SZJ + stage * FA_ZST + row * FA_ZROWB + half * 16;
        CP_ASYNC16(so,        g_zjh + zg);
        CP_ASYNC16(so + 1536, g_zjl + zg);
    }
    if (t < 8)
        CP_ASYNC16(sb + FA_STHJ + stage * 128 + t * 16,
                   g_th + (size_t)bh * 1024 + ch * 32 + t * 4);
}

__global__ __launch_bounds__(128, 3) void fused_attn(float* __restrict__ cp_out,
                                                     const float* __restrict__ p_cps,
                                                     const int* __restrict__ p_flag,
                                                     const int* __restrict__ p_dcmm) {
    extern __shared__ char sm[];
    const uint32_t sb = smem_u32(sm);
    const int t = threadIdx.x, wid = t >> 5, lane = t & 31;
    const int bh = blockIdx.x, m0 = blockIdx.y * 64;

    // Q tile (64 rows) + zB tile + thi (once)
    {
        const size_t qb = ((size_t)bh * 1024 + m0) * 64;
        #pragma unroll
        for (int i = 0; i < 4; i++) {
            const int u = t + i * 128;
            const int row = u >> 3, c = u & 7;
            *(uint4*)(sm + row * FA_QROWB + c * 16) =
                *(const uint4*)(g_qh + qb + row * 64 + c * 8);
            *(uint4*)(sm + 9216 + row * FA_QROWB + c * 16) =
                *(const uint4*)(g_ql + qb + row * 64 + c * 8);
        }
        const int row = t >> 1, half = t & 1;
        const size_t zg = ((size_t)bh * 1024 + m0 + row) * 16 + half * 8;
        *(uint4*)(sm + FA_SZBI + row * FA_ZROWB + half * 16) =
            *(const uint4*)(g_zbh + zg);
        *(uint4*)(sm + FA_SZBI + 3072 + row * FA_ZROWB + half * 16) =
            *(const uint4*)(g_zbl + zg);
    }
    if (t < 64)
        ((float*)(sm + FA_STHI))[t] = g_th[(size_t)bh * 1024 + m0 + t];
    fa_ld_chunk(sb, 0, bh, 0, t);
    CP_COMMIT();
    __syncthreads();

    // persistent zB fragments (Q frags reloaded per chunk)
    uint32_t azh[4], azl[4];
    const uint32_t a_row = wid * 16 + (lane & 15);
    const uint32_t a_kb  = (lane >> 4) * 16;
    {
        const uint32_t zr = sb + FA_SZBI + a_row * FA_ZROWB + a_kb;
        ldm_x4(azh[0], azh[1], azh[2], azh[3], zr);
        ldm_x4(azl[0], azl[1], azl[2], azl[3], zr + 3072);
    }
    const int er = lane >> 2;
    const int r0 = wid * 16 + er;
    const float gate = (p_flag[0] != 0 && p_dcmm[0] != 0) ? 1.0f : 0.0f;
    const float cps = p_cps[0] * gate;
    const float fi0 = cps * ((float*)(sm + FA_STHI))[r0];
    const float fi1 = cps * ((float*)(sm + FA_STHI))[r0 + 8];

    float o[8][4];
    #pragma unroll
    for (int ni = 0; ni < 8; ni++)
        #pragma unroll
        for (int r = 0; r < 4; r++) o[ni][r] = 0.0f;
    float mr0 = -1e30f, mr1 = -1e30f, lr0 = 0.0f, lr1 = 0.0f;

    const uint32_t b_row16 = (lane & 7) + ((lane >> 4) & 1) * 8;
    const uint32_t b_kb = ((lane >> 3) & 1) * 16;
    const int c0l = (lane & 3) * 2;
    const long long cpbase = (long long)bh << 20;

    for (int ch = 0; ch < 32; ch++) {
        CP_WAIT(0);
        __syncthreads();
        if (ch < 31) {
            fa_ld_chunk(sb, (ch + 1) & 1, bh, ch + 1, t);
            CP_COMMIT();
        }

        const uint32_t kst = sb + FA_SK + (ch & 1) * FA_KST;
        const uint32_t vst = sb + FA_SV + (ch & 1) * FA_VST;
        const uint32_t zjst = sb + FA_SZJ + (ch & 1) * FA_ZST;
        const float* thj = (const float*)(sm + FA_STHJ + (ch & 1) * 128);

        // ---- S = Q K^T (3-pass hi/lo) ----
        float s[4][4];
        #pragma unroll
        for (int ni = 0; ni < 4; ni++)
            #pragma unroll
            for (int r = 0; r < 4; r++) s[ni][r] = 0.0f;

        #pragma unroll
        for (int ks = 0; ks < 4; ks++) {
            uint32_t aqh[4], aql[4];
            const uint32_t ar = sb + a_row * FA_QROWB + ks * 32 + a_kb;
            ldm_x4(aqh[0], aqh[1], aqh[2], aqh[3], ar);
            ldm_x4(aql[0], aql[1], aql[2], aql[3], ar + 9216);
            #pragma unroll
            for (int np = 0; np < 2; np++) {
                uint32_t bkh[4], bkl[4];
                const uint32_t br = kst + (np * 16 + b_row16) * FA_KROWB + ks * 32 + b_kb;
                ldm_x4(bkh[0], bkh[1], bkh[2], bkh[3], br);
                ldm_x4(bkl[0], bkl[1], bkl[2], bkl[3], br + 4608);
                #pragma unroll
                for (int hh = 0; hh < 2; hh++) {
                    float* s4 = s[np * 2 + hh];
                    mma_bf16(s4, aqh, &bkh[hh * 2]);
                    mma_bf16(s4, aqh, &bkl[hh * 2]);
                    mma_bf16(s4, aql, &bkh[hh * 2]);
                }
            }
        }

        // ---- bias via MMA (zB @ z^T), tanh, cp write, chunk max ----
        float cmax0 = -1e30f, cmax1 = -1e30f;
        #pragma unroll
        for (int np = 0; np < 2; np++) {
            uint32_t zh4[4], zl4[4];
            const uint32_t zr = zjst + (np * 16 + b_row16) * FA_ZROWB + b_kb;
            ldm_x4(zh4[0], zh4[1], zh4[2], zh4[3], zr);
            ldm_x4(zl4[0], zl4[1], zl4[2], zl4[3], zr + 1536);
            #pragma unroll
            for (int hh = 0; hh < 2; hh++) {
                const int ni = np * 2 + hh;
                const int c0 = ni * 8 + c0l;
                float d[4] = {0.0f, 0.0f, 0.0f, 0.0f};
                mma_bf16(d, azh, &zh4[hh * 2]);
                mma_bf16(d, azh, &zl4[hh * 2]);
                mma_bf16(d, azl, &zh4[hh * 2]);
                const float th0 = thj[c0], th1 = thj[c0 + 1];
                const float b00 = fi0 * th0 * fast_tanh(d[0]);
                const float b01 = fi0 * th1 * fast_tanh(d[1]);
                const float b10 = fi1 * th0 * fast_tanh(d[2]);
                const float b11 = fi1 * th1 * fast_tanh(d[3]);
                const long long off = cpbase + (long long)(m0 + r0) * 1024 + ch * 32 + c0;
                cp_out[off] = b00; cp_out[off + 1] = b01;
                cp_out[off + 8192] = b10; cp_out[off + 8193] = b11;
                s[ni][0] = s[ni][0] * 0.125f + b00;
                s[ni][1] = s[ni][1] * 0.125f + b01;
                s[ni][2] = s[ni][2] * 0.125f + b10;
                s[ni][3] = s[ni][3] * 0.125f + b11;
                cmax0 = fmaxf(cmax0, fmaxf(s[ni][0], s[ni][1]));
                cmax1 = fmaxf(cmax1, fmaxf(s[ni][2], s[ni][3]));
            }
        }
        cmax0 = fmaxf(cmax0, __shfl_xor_sync(0xffffffffu, cmax0, 1));
        cmax0 = fmaxf(cmax0, __shfl_xor_sync(0xffffffffu, cmax0, 2));
        cmax1 = fmaxf(cmax1, __shfl_xor_sync(0xffffffffu, cmax1, 1));
        cmax1 = fmaxf(cmax1, __shfl_xor_sync(0xffffffffu, cmax1, 2));

        const float M0 = fmaxf(mr0, cmax0), M1 = fmaxf(mr1, cmax1);
        const float sc0 = __expf(mr0 - M0), sc1 = __expf(mr1 - M1);
        mr0 = M0; mr1 = M1;

        float ls0 = 0.0f, ls1 = 0.0f;
        #pragma unroll
        for (int ni = 0; ni < 4; ni++) {
            s[ni][0] = __expf(s[ni][0] - M0);
            s[ni][1] = __expf(s[ni][1] - M0);
            s[ni][2] = __expf(s[ni][2] - M1);
            s[ni][3] = __expf(s[ni][3] - M1);
            ls0 += s[ni][0] + s[ni][1];
            ls1 += s[ni][2] + s[ni][3];
        }
        ls0 += __shfl_xor_sync(0xffffffffu, ls0, 1);
        ls0 += __shfl_xor_sync(0xffffffffu, ls0, 2);
        ls1 += __shfl_xor_sync(0xffffffffu, ls1, 1);
        ls1 += __shfl_xor_sync(0xffffffffu, ls1, 2);
        lr0 = lr0 * sc0 + ls0;
        lr1 = lr1 * sc1 + ls1;
        #pragma unroll
        for (int ni = 0; ni < 8; ni++) {
            o[ni][0] *= sc0; o[ni][1] *= sc0;
            o[ni][2] *= sc1; o[ni][3] *= sc1;
        }

        // ---- O += P V (P frags built in registers) ----
        #pragma unroll
        for (int ks = 0; ks < 2; ks++) {
            uint32_t ah[4], al[4];
            pack_hl(s[2 * ks][0],     s[2 * ks][1],     ah[0], al[0]);
            pack_hl(s[2 * ks][2],     s[2 * ks][3],     ah[1], al[1]);
            pack_hl(s[2 * ks + 1][0], s[2 * ks + 1][1], ah[2], al[2]);
            pack_hl(s[2 * ks + 1][2], s[2 * ks + 1][3], ah[3], al[3]);
            #pragma unroll
            for (int np = 0; np < 4; np++) {
                uint32_t bvh[4], bvl[4];
                const uint32_t br = vst + (np * 16 + b_row16) * FA_VROWB + ks * 32 + b_kb;
                ldm_x4(bvh[0], bvh[1], bvh[2], bvh[3], br);
                ldm_x4(bvl[0], bvl[1], bvl[2], bvl[3], br + 5120);
                #pragma unroll
                for (int hh = 0; hh < 2; hh++) {
                    float* o4 = o[np * 2 + hh];
                    mma_bf16(o4, ah, &bvh[hh * 2]);
                    mma_bf16(o4, ah, &bvl[hh * 2]);
                    mma_bf16(o4, al, &bvh[hh * 2]);
                }
            }
        }
    }

    // ---- finalize O, write hi/lo bf16 ----
    const float inv0 = 1.0f / lr0, inv1 = 1.0f / lr1;
    const int b = bh >> 4, h = bh & 15;
    #pragma unroll
    for (int ni = 0; ni < 8; ni++) {
        const int d = ni * 8 + c0l;
        const size_t ro = ((size_t)(b * 1024 + m0 + r0)) * 1024 + h * 64 + d;
        uint32_t hi, lo;
        pack_hl(o[ni][0] * inv0, o[ni][1] * inv0, hi, lo);
        *(uint32_t*)&g_ohh[ro] = hi;
        *(uint32_t*)&g_ohl[ro] = lo;
        pack_hl(o[ni][2] * inv1, o[ni][3] * inv1, hi, lo);
        *(uint32_t*)&g_ohh[ro + 8 * 1024] = hi;
        *(uint32_t*)&g_ohl[ro + 8 * 1024] = lo;
    }
}

// ---------------- scalar outputs ---------------------------------------------
__global__ void finalize(float* __restrict__ out,
                         const int* __restrict__ p_flag,
                         const int* __restrict__ p_dcmm) {
    __shared__ float red[256];
    red[threadIdx.x] = g_zcp[threadIdx.x];
    __syncthreads();
    for (int s2 = 128; s2 > 0; s2 >>= 1) {
        if (threadIdx.x < s2) red[threadIdx.x] += red[threadIdx.x + s2];
        __syncthreads();
    }
    if (threadIdx.x == 0) {
        const float gate = (p_flag[0] != 0 && p_dcmm[0] != 0) ? 1.0f : 0.0f;
        out[4194304] = gate * red[0] * (1.0f / 65536.0f);
        out[4194305] = 0.0f;
        out[4194306] = 0.0f;
    }
}

// ---------------------------------------------------------------------------
extern "C" void kernel_launch(void* const* d_in, const int* in_sizes, int n_in,
                              void* d_out, int out_size) {
    const float* x     = (const float*)d_in[0];
    const float* Wqkv  = (const float*)d_in[1];
    const float* Wproj = (const float*)d_in[2];
    const float* bproj = (const float*)d_in[3];
    const float* Wg    = (const float*)d_in[4];
    const float* bg    = (const float*)d_in[5];
    const float* Wt    = (const float*)d_in[6];
    const float* bt    = (const float*)d_in[7];
    const float* affB  = (const float*)d_in[8];
    const float* cps   = (const float*)d_in[9];
    const int*   flag  = (const int*)d_in[10];
    const int*   dcmm  = (const int*)d_in[12];

    float* out = (float*)d_out;
    float* cp  = out + 4194307;

    cudaFuncSetAttribute(mma_gemm, cudaFuncAttributeMaxDynamicSharedMemorySize, MMA_SMEM);
    cudaFuncSetAttribute(fused_attn, cudaFuncAttributeMaxDynamicSharedMemorySize, FA_SMEM);

    prep_all<<<4096 + 3072, 256>>>(x, Wqkv);
    mma_gemm<<<dim3(24, 32), 256, MMA_SMEM>>>(nullptr, nullptr, 0);
    zv_kernel<<<256 + 2048, 256>>>(Wg, bg, Wt, bt, affB);
    fused_attn<<<dim3(64, 16), 128, FA_SMEM>>>(cp, cps, flag, dcmm);
    transW<<<dim3(32, 32), dim3(32, 8)>>>(Wproj);
    mma_gemm<<<dim3(8, 32), 256, MMA_SMEM>>>(bproj, out, 1);
    finalize<<<1, 256>>>(out, flag, dcmm);
}